// round 2
// baseline (speedup 1.0000x reference)
#include <cuda_runtime.h>
#include <cuda_bf16.h>

// HybridQLSTM_65481071409480 — GB300 (sm_103a)
//
// Algebraic collapse: the reference ends with
//     log_softmax(broadcast_to(expectation[..., None], (S, B, T)), axis=-1)
// i.e. log_softmax over a CONSTANT row of length T=50. For a constant row e:
//     log_softmax = e - logsumexp(e*1_T) = e - (e + log T) = -log T
// independent of e. The embedding gather, 512-step LSTM scan, and sin()
// expectation are all dead code. JAX's stabilized log_softmax evaluates
// (x - max) - log(sum(exp(x - max))) = 0 - log(50) in fp32, so emitting the
// fp32-nearest value of -log(50) matches to ~1 ulp (rel_err ~1e-7, far under
// the 1e-3 gate).
//
// Optimal kernel: 3.125 MiB constant fill (819200 floats), write-only.
// float4 stores, exactly one store per thread in the expected shape
// (800 CTAs x 256 threads x 16 B = 3.125 MiB), grid-stride fallback for
// robustness to other sizes.

__global__ void fill_neglog50_kernel(float4* __restrict__ out4, int n4,
                                     float* __restrict__ out_tail, int n_tail) {
    const float v = -3.9120230674743652f;  // fp32-nearest -log(50)
    const float4 v4 = make_float4(v, v, v, v);
    int idx = blockIdx.x * blockDim.x + threadIdx.x;
    int stride = gridDim.x * blockDim.x;
    // Common case (n4 <= stride): loop executes exactly once per in-range
    // thread -> pure IMAD + STG.E.128 body, no live loop-carried state.
    for (int i = idx; i < n4; i += stride) {
        out4[i] = v4;
    }
    // Tail for out_size % 4 != 0 (0 for this problem, kept for robustness).
    if (idx < n_tail) {
        out_tail[idx] = v;
    }
}

extern "C" void kernel_launch(void* const* d_in, const int* in_sizes, int n_in,
                              void* d_out, int out_size) {
    (void)d_in; (void)in_sizes; (void)n_in;
    if (out_size <= 0) return;

    float* out = (float*)d_out;
    int n4 = out_size >> 2;           // 204800 for out_size = 819200
    int n_tail = out_size & 3;        // 0 here
    float* tail_ptr = out + (size_t)n4 * 4;

    const int threads = 256;
    int blocks = (n4 + threads - 1) / threads;   // 800 for this problem
    if (blocks > 65535) blocks = 65535;          // grid-stride covers overflow
    if (blocks < 1) blocks = 1;                  // n4==0 but tail>0

    fill_neglog50_kernel<<<blocks, threads>>>(
        (float4*)out, n4, tail_ptr, n_tail);
}